// round 14
// baseline (speedup 1.0000x reference)
#include <cuda_runtime.h>
#include <math.h>

#define N_PTS 65536
#define KKEY 64
#define NT 512
#define GRID_SCORE 128   // 128 blocks x 512 threads = 65536 points, 1 pt/thread

typedef unsigned long long u64;

// scratch (no allocations allowed) — referenced ONLY from device code
__device__ u64 g_cand[GRID_SCORE * KKEY];   // 8192 (128 sorted-64 lists)
__device__ unsigned g_done;                  // zero-init; reset by elected block

// ---------------------------------------------------------------------------
// packed f32x2 helpers (FFMA2: 2 fp32 FMAs per instruction, only via PTX)
// ---------------------------------------------------------------------------
__device__ __forceinline__ u64 fma2(u64 a, u64 b, u64 c) {
    u64 d;
    asm("fma.rn.f32x2 %0, %1, %2, %3;" : "=l"(d) : "l"(a), "l"(b), "l"(c));
    return d;
}
__device__ __forceinline__ u64 add2(u64 a, u64 b) {
    u64 d;
    asm("add.rn.f32x2 %0, %1, %2;" : "=l"(d) : "l"(a), "l"(b));
    return d;
}
__device__ __forceinline__ u64 pack2(float lo, float hi) {
    u64 r;
    asm("mov.b64 %0, {%1, %2};" : "=l"(r) : "f"(lo), "f"(hi));
    return r;
}
__device__ __forceinline__ void unpack2(u64 x, float& lo, float& hi) {
    asm("mov.b64 {%0, %1}, %2;" : "=f"(lo), "=f"(hi) : "l"(x));
}
__device__ __forceinline__ u64 relu2(u64 x) {
    float lo, hi;
    unpack2(x, lo, hi);
    return pack2(fmaxf(lo, 0.0f), fmaxf(hi, 0.0f));
}

// ---------------------------------------------------------------------------
// bitonic compare-select, element at global position i, descending sort.
// Keys unique (low bits = ~index) so strict compare is fine.
// ---------------------------------------------------------------------------
__device__ __forceinline__ u64 cmpsel(u64 v, u64 pv, int i, int k, int j) {
    bool keep_max = (((i & k) == 0) == ((i & j) == 0));
    u64 mx = v > pv ? v : pv;
    u64 mn = v > pv ? pv : v;
    return keep_max ? mx : mn;
}

// ---------------------------------------------------------------------------
// warp-local sort of 64 elements (v0 = pos lane, v1 = pos lane+32),
// descending, barrier-free (shfl only; j==32 is in-thread).
// ---------------------------------------------------------------------------
__device__ __forceinline__ void warp_sort64(u64& v0, u64& v1, int lane) {
#pragma unroll
    for (int k = 2; k <= 64; k <<= 1) {
#pragma unroll
        for (int j = k >> 1; j > 0; j >>= 1) {
            if (j == 32) {
                bool dirdesc = ((lane & k) == 0);
                u64 mx = v0 > v1 ? v0 : v1;
                u64 mn = v0 > v1 ? v1 : v0;
                v0 = dirdesc ? mx : mn;
                v1 = dirdesc ? mn : mx;
            } else {
                u64 p0 = __shfl_xor_sync(0xffffffffu, v0, j);
                u64 p1 = __shfl_xor_sync(0xffffffffu, v1, j);
                v0 = cmpsel(v0, p0, lane, k, j);
                v1 = cmpsel(v1, p1, lane + 32, k, j);
            }
        }
    }
}

// ---------------------------------------------------------------------------
// merge two sorted-descending 64-lists, keeping the sorted top-64 in (a0,a1).
// w[i] = max(A[i], B[63-i]) is bitonic and contains the top-64; then a
// 6-substage descending bitonic merge. Barrier-free.
// ---------------------------------------------------------------------------
__device__ __forceinline__ void warp_merge64(u64& a0, u64& a1, u64 b0, u64 b1,
                                             int lane) {
    u64 rb1 = __shfl_sync(0xffffffffu, b1, 31 - lane);  // B[63-lane]
    u64 rb0 = __shfl_sync(0xffffffffu, b0, 31 - lane);  // B[63-(lane+32)]
    u64 w0 = a0 > rb1 ? a0 : rb1;
    u64 w1 = a1 > rb0 ? a1 : rb0;
    {
        u64 mx = w0 > w1 ? w0 : w1;
        u64 mn = w0 > w1 ? w1 : w0;
        w0 = mx; w1 = mn;
    }
#pragma unroll
    for (int j = 16; j > 0; j >>= 1) {
        u64 p0 = __shfl_xor_sync(0xffffffffu, w0, j);
        u64 p1 = __shfl_xor_sync(0xffffffffu, w1, j);
        bool low = ((lane & j) == 0);
        w0 = low ? (w0 > p0 ? w0 : p0) : (w0 < p0 ? w0 : p0);
        w1 = low ? (w1 > p1 ? w1 : p1) : (w1 < p1 ? w1 : p1);
    }
    a0 = w0; a1 = w1;
}

// ---------------------------------------------------------------------------
// ONE kernel: MLP score (R13-verbatim math) + per-block top-64 + last-
// finisher election; the 128th block merges all 128 sorted lists + gathers.
// key = (bits(softplus) << 32) | ~n  (sp > 0 so bits are order-monotonic)
// ---------------------------------------------------------------------------
__global__ __launch_bounds__(NT) void fused_kernel(
    const float* __restrict__ src,
    const float* __restrict__ W1, const float* __restrict__ b1,
    const float* __restrict__ W2, const float* __restrict__ b2,
    const float* __restrict__ Wa, const float* __restrict__ ba,
    const float* __restrict__ Wb, const float* __restrict__ bb_,
    const float* __restrict__ Wc, const float* __restrict__ bc,
    float* __restrict__ out)
{
    __shared__ __align__(16) u64 sW1p[96];     // [i<16][c<6] = (W1[2i,c], W1[2i+1,c])
    __shared__ __align__(16) u64 sW2p[1024];   // [j<64][i<16] = (W2[j,2i], W2[j,2i+1])
    __shared__ __align__(16) u64 sWaJp[512];   // [jp<32][i<16] = (Wa[i,2jp], Wa[i,2jp+1])
    __shared__ __align__(16) u64 sWbp[64];     // [i<4][k<16] = (Wb[2i,k], Wb[2i+1,k])
    __shared__ __align__(16) u64 sWcp[4];      // (Wc[2i], Wc[2i+1])
    __shared__ u64 sb1p[16];                   // (b1[2i], b1[2i+1])
    __shared__ u64 sb2p[32];                   // (b2[2jp], b2[2jp+1])
    __shared__ float sba[16];
    __shared__ u64 sbbp[4];
    __shared__ float sbc;
    __shared__ u64 s_keys[NT];
    __shared__ int sidx[KKEY];
    __shared__ unsigned s_old;

    const int t = threadIdx.x;
    const int blk = blockIdx.x;
    const int lane = t & 31;
    const int w = t >> 5;

    // W2 rows are contiguous fp32 -> natural u64 pairs, direct copy
    for (int i = t; i < 1024; i += NT)
        sW2p[i] = ((const u64*)W2)[i];
    for (int idx = t; idx < 512; idx += NT) {
        int jp = idx >> 4, i = idx & 15;
        sWaJp[idx] = pack2(Wa[i * 64 + 2 * jp], Wa[i * 64 + 2 * jp + 1]);
    }
    if (t < 96) {
        int i = t / 6, c = t % 6;
        sW1p[t] = pack2(W1[(2 * i) * 6 + c], W1[(2 * i + 1) * 6 + c]);
    }
    if (t >= 96 && t < 112)  sb1p[t - 96] = pack2(b1[2 * (t - 96)], b1[2 * (t - 96) + 1]);
    if (t >= 112 && t < 128) sba[t - 112] = ba[t - 112];
    if (t >= 128 && t < 192) {
        int idx = t - 128;
        int i = idx >> 4, k = idx & 15;
        sWbp[idx] = pack2(Wb[(2 * i) * 16 + k], Wb[(2 * i + 1) * 16 + k]);
    }
    if (t >= 192 && t < 224) sb2p[t - 192] = ((const u64*)b2)[t - 192];
    if (t >= 224 && t < 228) sbbp[t - 224] = pack2(bb_[2 * (t - 224)], bb_[2 * (t - 224) + 1]);
    if (t >= 228 && t < 232) sWcp[t - 228] = pack2(Wc[2 * (t - 228)], Wc[2 * (t - 228) + 1]);
    if (t == 0) sbc = bc[0];
    __syncthreads();

    const int n = blk * NT + t;   // point id

    u64 xd[6];
#pragma unroll
    for (int c = 0; c < 6; c++) {
        float xv = src[c * N_PTS + n];
        xd[c] = pack2(xv, xv);
    }

    // layer 1: 6 -> 32 (as 16 neuron-pairs), relu
    u64 h1p[16];
#pragma unroll
    for (int i = 0; i < 16; i++) {
        const ulonglong2* wq = (const ulonglong2*)(sW1p + i * 6);
        ulonglong2 q0 = wq[0], q1 = wq[1], q2 = wq[2];
        u64 v = sb1p[i];
        v = fma2(q0.x, xd[0], v);
        v = fma2(q0.y, xd[1], v);
        v = fma2(q1.x, xd[2], v);
        v = fma2(q1.y, xd[3], v);
        v = fma2(q2.x, xd[4], v);
        v = fma2(q2.y, xd[5], v);
        h1p[i] = relu2(v);
    }

    // layer 2 (32->64, relu) fused with layer a (64->16): j-paired
    u64 ap[16];
#pragma unroll
    for (int i = 0; i < 16; i++) ap[i] = pack2(sba[i], 0.0f);

#pragma unroll 2
    for (int jp = 0; jp < 32; jp++) {
        const ulonglong2* w2 = (const ulonglong2*)(sW2p + (2 * jp) * 16);
        u64 cA0 = 0ULL, cA1 = 0ULL, cB0 = 0ULL, cB1 = 0ULL;
#pragma unroll
        for (int i = 0; i < 16; i += 4) {
            ulonglong2 qa0 = w2[i / 2];
            ulonglong2 qa1 = w2[i / 2 + 1];
            ulonglong2 qb0 = w2[8 + i / 2];
            ulonglong2 qb1 = w2[8 + i / 2 + 1];
            cA0 = fma2(qa0.x, h1p[i],     cA0);
            cA1 = fma2(qa0.y, h1p[i + 1], cA1);
            cA0 = fma2(qa1.x, h1p[i + 2], cA0);
            cA1 = fma2(qa1.y, h1p[i + 3], cA1);
            cB0 = fma2(qb0.x, h1p[i],     cB0);
            cB1 = fma2(qb0.y, h1p[i + 1], cB1);
            cB0 = fma2(qb1.x, h1p[i + 2], cB0);
            cB1 = fma2(qb1.y, h1p[i + 3], cB1);
        }
        u64 sA = add2(cA0, cA1);
        u64 sB = add2(cB0, cB1);
        float alo, ahi, blo, bhi;
        unpack2(sA, alo, ahi);
        unpack2(sB, blo, bhi);
        u64 sum = add2(add2(pack2(alo, blo), pack2(ahi, bhi)), sb2p[jp]);
        float v0f, v1f;
        unpack2(sum, v0f, v1f);
        u64 vd = pack2(fmaxf(v0f, 0.0f), fmaxf(v1f, 0.0f));

        const ulonglong2* wa = (const ulonglong2*)(sWaJp + jp * 16);
#pragma unroll
        for (int i = 0; i < 16; i += 2) {
            ulonglong2 q = wa[i / 2];
            ap[i]     = fma2(q.x, vd, ap[i]);
            ap[i + 1] = fma2(q.y, vd, ap[i + 1]);
        }
    }

    // horizontalize layer-a accumulators; relu; dup for layer b
    u64 afd[16];
#pragma unroll
    for (int i = 0; i < 16; i++) {
        float lo, hi;
        unpack2(ap[i], lo, hi);
        float av = fmaxf(lo + hi, 0.0f);
        afd[i] = pack2(av, av);
    }

    // layer b: 16 -> 8 (as 4 neuron-pairs), relu
    u64 hbp[4];
#pragma unroll
    for (int i = 0; i < 4; i++) {
        const ulonglong2* wb = (const ulonglong2*)(sWbp + i * 16);
        u64 s0 = sbbp[i], s1 = 0ULL;
#pragma unroll
        for (int k = 0; k < 16; k += 4) {
            ulonglong2 q0 = wb[k / 2];
            ulonglong2 q1 = wb[k / 2 + 1];
            s0 = fma2(q0.x, afd[k],     s0);
            s1 = fma2(q0.y, afd[k + 1], s1);
            s0 = fma2(q1.x, afd[k + 2], s0);
            s1 = fma2(q1.y, afd[k + 3], s1);
        }
        hbp[i] = relu2(add2(s0, s1));
    }

    // layer c: 8 -> 1, softplus = max(x,0)+log1p(exp(-|x|))
    u64 cp = 0ULL;
#pragma unroll
    for (int i = 0; i < 4; i++) cp = fma2(sWcp[i], hbp[i], cp);
    float clo, chi;
    unpack2(cp, clo, chi);
    float c0f = sbc + (clo + chi);
    float sp = fmaxf(c0f, 0.0f) + log1pf(expf(-fabsf(c0f)));

    s_keys[t] = ((u64)__float_as_uint(sp) << 32) | (unsigned int)(~n);
    __syncthreads();

    // selection: warps 0..7 sort 64-chunks, then 3 merge levels -> top-64
    {
        u64 v0 = 0ULL, v1 = 0ULL;
        if (w < 8) {
            v0 = s_keys[w * 64 + lane];
            v1 = s_keys[w * 64 + 32 + lane];
            warp_sort64(v0, v1, lane);
        }
        for (int nl = 8; nl > 1; nl >>= 1) {
            int half = nl >> 1;
            __syncthreads();
            if (w >= half && w < nl) {
                s_keys[(w - half) * 64 + lane] = v0;
                s_keys[(w - half) * 64 + 32 + lane] = v1;
            }
            __syncthreads();
            if (w < half) {
                u64 b0 = s_keys[w * 64 + lane];
                u64 b1 = s_keys[w * 64 + 32 + lane];
                warp_merge64(v0, v1, b0, b1, lane);
            }
        }
        if (w == 0) {
            g_cand[blk * KKEY + lane] = v0;
            g_cand[blk * KKEY + 32 + lane] = v1;
        }
    }

    // ---- election: last block to finish does the global merge + gather ----
    __threadfence();
    __syncthreads();
    if (t == 0) s_old = atomicAdd(&g_done, 1u);
    __syncthreads();
    if (s_old != GRID_SCORE - 1) return;
    __threadfence();

    // merge 128 sorted lists: each warp folds 8 lists, then 4 block levels
    {
        const u64* base = g_cand + (w * 8) * KKEY;
        u64 v0 = base[lane];
        u64 v1 = base[32 + lane];
#pragma unroll
        for (int l = 1; l < 8; l++) {
            u64 b0 = base[l * KKEY + lane];
            u64 b1 = base[l * KKEY + 32 + lane];
            warp_merge64(v0, v1, b0, b1, lane);
        }

        for (int nl = 16; nl > 1; nl >>= 1) {
            int half = nl >> 1;
            __syncthreads();
            if (w >= half && w < nl) {
                s_keys[(w - half) * 64 + lane] = v0;
                s_keys[(w - half) * 64 + 32 + lane] = v1;
            }
            __syncthreads();
            if (w < half) {
                u64 b0 = s_keys[w * 64 + lane];
                u64 b1 = s_keys[w * 64 + 32 + lane];
                warp_merge64(v0, v1, b0, b1, lane);
            }
        }
        if (w == 0) {
            sidx[lane]      = (int)(~(unsigned int)v0);
            sidx[lane + 32] = (int)(~(unsigned int)v1);
        }
    }
    __syncthreads();

    // fused gather: out[b,k,c] = src_pts[b, c, idx[k]]   (8,64,6) row-major
#pragma unroll
    for (int o = t; o < 8 * KKEY * 6; o += NT) {
        int c = o % 6;
        int k = (o / 6) & (KKEY - 1);
        int b = o / (6 * KKEY);
        out[o] = src[(b * 6 + c) * N_PTS + sidx[k]];
    }

    __syncthreads();
    if (t == 0) g_done = 0u;   // reset for graph replay; elected block is last
}

// ---------------------------------------------------------------------------
extern "C" void kernel_launch(void* const* d_in, const int* in_sizes, int n_in,
                              void* d_out, int out_size)
{
    const float* src = (const float*)d_in[0];   // src_pts (8,6,65536)
    // d_in[1] = tgt_pts (unused)
    const float* W1 = (const float*)d_in[2];
    const float* b1 = (const float*)d_in[3];
    const float* W2 = (const float*)d_in[4];
    const float* b2 = (const float*)d_in[5];
    const float* Wa = (const float*)d_in[6];
    const float* ba = (const float*)d_in[7];
    const float* Wb = (const float*)d_in[8];
    const float* bb = (const float*)d_in[9];
    const float* Wc = (const float*)d_in[10];
    const float* bc = (const float*)d_in[11];
    float* out = (float*)d_out;

    fused_kernel<<<GRID_SCORE, NT>>>(
        src, W1, b1, W2, b2, Wa, ba, Wb, bb, Wc, bc, out);
}

// round 15
// speedup vs baseline: 1.0662x; 1.0662x over previous
#include <cuda_runtime.h>
#include <math.h>

#define N_PTS 65536
#define KKEY 64
#define NT 512
#define GRID_SCORE 128   // 128 blocks x 512 threads = 65536 points, 1 pt/thread

typedef unsigned long long u64;

// scratch (no allocations allowed) — referenced ONLY from device code
__device__ u64 g_cand[GRID_SCORE * KKEY];   // 8192 (128 sorted-64 lists)

// ---------------------------------------------------------------------------
// packed f32x2 helpers (FFMA2: 2 fp32 FMAs per instruction, only via PTX)
// ---------------------------------------------------------------------------
__device__ __forceinline__ u64 fma2(u64 a, u64 b, u64 c) {
    u64 d;
    asm("fma.rn.f32x2 %0, %1, %2, %3;" : "=l"(d) : "l"(a), "l"(b), "l"(c));
    return d;
}
__device__ __forceinline__ u64 add2(u64 a, u64 b) {
    u64 d;
    asm("add.rn.f32x2 %0, %1, %2;" : "=l"(d) : "l"(a), "l"(b));
    return d;
}
__device__ __forceinline__ u64 pack2(float lo, float hi) {
    u64 r;
    asm("mov.b64 %0, {%1, %2};" : "=l"(r) : "f"(lo), "f"(hi));
    return r;
}
__device__ __forceinline__ void unpack2(u64 x, float& lo, float& hi) {
    asm("mov.b64 {%0, %1}, %2;" : "=f"(lo), "=f"(hi) : "l"(x));
}
__device__ __forceinline__ u64 relu2(u64 x) {
    float lo, hi;
    unpack2(x, lo, hi);
    return pack2(fmaxf(lo, 0.0f), fmaxf(hi, 0.0f));
}

// ---------------------------------------------------------------------------
// bitonic compare-select, element at global position i, descending sort.
// Keys unique (low bits = ~index) so strict compare is fine.
// ---------------------------------------------------------------------------
__device__ __forceinline__ u64 cmpsel(u64 v, u64 pv, int i, int k, int j) {
    bool keep_max = (((i & k) == 0) == ((i & j) == 0));
    u64 mx = v > pv ? v : pv;
    u64 mn = v > pv ? pv : v;
    return keep_max ? mx : mn;
}

// ---------------------------------------------------------------------------
// warp-local sort of 64 elements (v0 = pos lane, v1 = pos lane+32),
// descending, barrier-free (shfl only; j==32 is in-thread).
// ---------------------------------------------------------------------------
__device__ __forceinline__ void warp_sort64(u64& v0, u64& v1, int lane) {
#pragma unroll
    for (int k = 2; k <= 64; k <<= 1) {
#pragma unroll
        for (int j = k >> 1; j > 0; j >>= 1) {
            if (j == 32) {
                bool dirdesc = ((lane & k) == 0);
                u64 mx = v0 > v1 ? v0 : v1;
                u64 mn = v0 > v1 ? v1 : v0;
                v0 = dirdesc ? mx : mn;
                v1 = dirdesc ? mn : mx;
            } else {
                u64 p0 = __shfl_xor_sync(0xffffffffu, v0, j);
                u64 p1 = __shfl_xor_sync(0xffffffffu, v1, j);
                v0 = cmpsel(v0, p0, lane, k, j);
                v1 = cmpsel(v1, p1, lane + 32, k, j);
            }
        }
    }
}

// ---------------------------------------------------------------------------
// merge two sorted-descending 64-lists, keeping the sorted top-64 in (a0,a1).
// w[i] = max(A[i], B[63-i]) is bitonic and contains the top-64; then a
// 6-substage descending bitonic merge. Barrier-free.
// ---------------------------------------------------------------------------
__device__ __forceinline__ void warp_merge64(u64& a0, u64& a1, u64 b0, u64 b1,
                                             int lane) {
    u64 rb1 = __shfl_sync(0xffffffffu, b1, 31 - lane);  // B[63-lane]
    u64 rb0 = __shfl_sync(0xffffffffu, b0, 31 - lane);  // B[63-(lane+32)]
    u64 w0 = a0 > rb1 ? a0 : rb1;
    u64 w1 = a1 > rb0 ? a1 : rb0;
    {
        u64 mx = w0 > w1 ? w0 : w1;
        u64 mn = w0 > w1 ? w1 : w0;
        w0 = mx; w1 = mn;
    }
#pragma unroll
    for (int j = 16; j > 0; j >>= 1) {
        u64 p0 = __shfl_xor_sync(0xffffffffu, w0, j);
        u64 p1 = __shfl_xor_sync(0xffffffffu, w1, j);
        bool low = ((lane & j) == 0);
        w0 = low ? (w0 > p0 ? w0 : p0) : (w0 < p0 ? w0 : p0);
        w1 = low ? (w1 > p1 ? w1 : p1) : (w1 < p1 ? w1 : p1);
    }
    a0 = w0; a1 = w1;
}

// ---------------------------------------------------------------------------
// Kernel 1: MLP score (batch 0), ONE point per thread (R13-verbatim).
// Selection: warps 0..7 warp-sort-64 their chunk, then 3 merge levels ->
// sorted block top-64 into g_cand.
// key = (bits(softplus) << 32) | ~n  (sp > 0 so bits are order-monotonic)
// ---------------------------------------------------------------------------
__global__ __launch_bounds__(NT) void score_kernel(
    const float* __restrict__ src,
    const float* __restrict__ W1, const float* __restrict__ b1,
    const float* __restrict__ W2, const float* __restrict__ b2,
    const float* __restrict__ Wa, const float* __restrict__ ba,
    const float* __restrict__ Wb, const float* __restrict__ bb_,
    const float* __restrict__ Wc, const float* __restrict__ bc)
{
    __shared__ __align__(16) u64 sW1p[96];     // [i<16][c<6] = (W1[2i,c], W1[2i+1,c])
    __shared__ __align__(16) u64 sW2p[1024];   // [j<64][i<16] = (W2[j,2i], W2[j,2i+1])
    __shared__ __align__(16) u64 sWaJp[512];   // [jp<32][i<16] = (Wa[i,2jp], Wa[i,2jp+1])
    __shared__ __align__(16) u64 sWbp[64];     // [i<4][k<16] = (Wb[2i,k], Wb[2i+1,k])
    __shared__ __align__(16) u64 sWcp[4];      // (Wc[2i], Wc[2i+1])
    __shared__ u64 sb1p[16];                   // (b1[2i], b1[2i+1])
    __shared__ u64 sb2p[32];                   // (b2[2jp], b2[2jp+1])
    __shared__ float sba[16];
    __shared__ u64 sbbp[4];
    __shared__ float sbc;
    __shared__ u64 s_keys[NT];

    const int t = threadIdx.x;
    const int blk = blockIdx.x;
    const int lane = t & 31;
    const int w = t >> 5;

    // W2 rows are contiguous fp32 -> natural u64 pairs, direct copy
    for (int i = t; i < 1024; i += NT)
        sW2p[i] = ((const u64*)W2)[i];
    for (int idx = t; idx < 512; idx += NT) {
        int jp = idx >> 4, i = idx & 15;
        sWaJp[idx] = pack2(Wa[i * 64 + 2 * jp], Wa[i * 64 + 2 * jp + 1]);
    }
    if (t < 96) {
        int i = t / 6, c = t % 6;
        sW1p[t] = pack2(W1[(2 * i) * 6 + c], W1[(2 * i + 1) * 6 + c]);
    }
    if (t >= 96 && t < 112)  sb1p[t - 96] = pack2(b1[2 * (t - 96)], b1[2 * (t - 96) + 1]);
    if (t >= 112 && t < 128) sba[t - 112] = ba[t - 112];
    if (t >= 128 && t < 192) {
        int idx = t - 128;
        int i = idx >> 4, k = idx & 15;
        sWbp[idx] = pack2(Wb[(2 * i) * 16 + k], Wb[(2 * i + 1) * 16 + k]);
    }
    if (t >= 192 && t < 224) sb2p[t - 192] = ((const u64*)b2)[t - 192];
    if (t >= 224 && t < 228) sbbp[t - 224] = pack2(bb_[2 * (t - 224)], bb_[2 * (t - 224) + 1]);
    if (t >= 228 && t < 232) sWcp[t - 228] = pack2(Wc[2 * (t - 228)], Wc[2 * (t - 228) + 1]);
    if (t == 0) sbc = bc[0];
    __syncthreads();

    const int n = blk * NT + t;   // point id

    u64 xd[6];
#pragma unroll
    for (int c = 0; c < 6; c++) {
        float xv = src[c * N_PTS + n];
        xd[c] = pack2(xv, xv);
    }

    // layer 1: 6 -> 32 (as 16 neuron-pairs), relu
    u64 h1p[16];
#pragma unroll
    for (int i = 0; i < 16; i++) {
        const ulonglong2* wq = (const ulonglong2*)(sW1p + i * 6);
        ulonglong2 q0 = wq[0], q1 = wq[1], q2 = wq[2];
        u64 v = sb1p[i];
        v = fma2(q0.x, xd[0], v);
        v = fma2(q0.y, xd[1], v);
        v = fma2(q1.x, xd[2], v);
        v = fma2(q1.y, xd[3], v);
        v = fma2(q2.x, xd[4], v);
        v = fma2(q2.y, xd[5], v);
        h1p[i] = relu2(v);
    }

    // layer 2 (32->64, relu) fused with layer a (64->16): j-paired
    u64 ap[16];
#pragma unroll
    for (int i = 0; i < 16; i++) ap[i] = pack2(sba[i], 0.0f);

#pragma unroll 2
    for (int jp = 0; jp < 32; jp++) {
        const ulonglong2* w2 = (const ulonglong2*)(sW2p + (2 * jp) * 16);
        u64 cA0 = 0ULL, cA1 = 0ULL, cB0 = 0ULL, cB1 = 0ULL;
#pragma unroll
        for (int i = 0; i < 16; i += 4) {
            ulonglong2 qa0 = w2[i / 2];
            ulonglong2 qa1 = w2[i / 2 + 1];
            ulonglong2 qb0 = w2[8 + i / 2];
            ulonglong2 qb1 = w2[8 + i / 2 + 1];
            cA0 = fma2(qa0.x, h1p[i],     cA0);
            cA1 = fma2(qa0.y, h1p[i + 1], cA1);
            cA0 = fma2(qa1.x, h1p[i + 2], cA0);
            cA1 = fma2(qa1.y, h1p[i + 3], cA1);
            cB0 = fma2(qb0.x, h1p[i],     cB0);
            cB1 = fma2(qb0.y, h1p[i + 1], cB1);
            cB0 = fma2(qb1.x, h1p[i + 2], cB0);
            cB1 = fma2(qb1.y, h1p[i + 3], cB1);
        }
        u64 sA = add2(cA0, cA1);
        u64 sB = add2(cB0, cB1);
        float alo, ahi, blo, bhi;
        unpack2(sA, alo, ahi);
        unpack2(sB, blo, bhi);
        u64 sum = add2(add2(pack2(alo, blo), pack2(ahi, bhi)), sb2p[jp]);
        float v0f, v1f;
        unpack2(sum, v0f, v1f);
        u64 vd = pack2(fmaxf(v0f, 0.0f), fmaxf(v1f, 0.0f));

        const ulonglong2* wa = (const ulonglong2*)(sWaJp + jp * 16);
#pragma unroll
        for (int i = 0; i < 16; i += 2) {
            ulonglong2 q = wa[i / 2];
            ap[i]     = fma2(q.x, vd, ap[i]);
            ap[i + 1] = fma2(q.y, vd, ap[i + 1]);
        }
    }

    // horizontalize layer-a accumulators; relu; dup for layer b
    u64 afd[16];
#pragma unroll
    for (int i = 0; i < 16; i++) {
        float lo, hi;
        unpack2(ap[i], lo, hi);
        float av = fmaxf(lo + hi, 0.0f);
        afd[i] = pack2(av, av);
    }

    // layer b: 16 -> 8 (as 4 neuron-pairs), relu
    u64 hbp[4];
#pragma unroll
    for (int i = 0; i < 4; i++) {
        const ulonglong2* wb = (const ulonglong2*)(sWbp + i * 16);
        u64 s0 = sbbp[i], s1 = 0ULL;
#pragma unroll
        for (int k = 0; k < 16; k += 4) {
            ulonglong2 q0 = wb[k / 2];
            ulonglong2 q1 = wb[k / 2 + 1];
            s0 = fma2(q0.x, afd[k],     s0);
            s1 = fma2(q0.y, afd[k + 1], s1);
            s0 = fma2(q1.x, afd[k + 2], s0);
            s1 = fma2(q1.y, afd[k + 3], s1);
        }
        hbp[i] = relu2(add2(s0, s1));
    }

    // layer c: 8 -> 1, softplus = max(x,0)+log1p(exp(-|x|))
    u64 cp = 0ULL;
#pragma unroll
    for (int i = 0; i < 4; i++) cp = fma2(sWcp[i], hbp[i], cp);
    float clo, chi;
    unpack2(cp, clo, chi);
    float c0f = sbc + (clo + chi);
    float sp = fmaxf(c0f, 0.0f) + log1pf(expf(-fabsf(c0f)));

    s_keys[t] = ((u64)__float_as_uint(sp) << 32) | (unsigned int)(~n);
    __syncthreads();

    // selection: warps 0..7 sort 64-chunks, then 3 merge levels -> top-64
    {
        u64 v0 = 0ULL, v1 = 0ULL;
        if (w < 8) {
            v0 = s_keys[w * 64 + lane];
            v1 = s_keys[w * 64 + 32 + lane];
            warp_sort64(v0, v1, lane);
        }
        for (int nl = 8; nl > 1; nl >>= 1) {
            int half = nl >> 1;
            __syncthreads();
            if (w >= half && w < nl) {
                s_keys[(w - half) * 64 + lane] = v0;
                s_keys[(w - half) * 64 + 32 + lane] = v1;
            }
            __syncthreads();
            if (w < half) {
                u64 b0 = s_keys[w * 64 + lane];
                u64 b1 = s_keys[w * 64 + 32 + lane];
                warp_merge64(v0, v1, b0, b1, lane);
            }
        }
        if (w == 0) {
            g_cand[blk * KKEY + lane] = v0;
            g_cand[blk * KKEY + 32 + lane] = v1;
        }
    }
}

// ---------------------------------------------------------------------------
// Tail: ONE block, 512 threads. Each of 16 warps folds 8 sorted-64 lists
// (7 barrier-free merges), then 4 block-level merge rounds -> global sorted
// top-64, then the fused gather. ~1.5us of work, single launch.
// ---------------------------------------------------------------------------
__global__ __launch_bounds__(512) void tail_kernel(
    const float* __restrict__ src, float* __restrict__ out)
{
    __shared__ u64 sx[512];
    __shared__ int sidx[KKEY];
    const int t = threadIdx.x;
    const int lane = t & 31;
    const int w = t >> 5;

    // each warp folds lists [8w, 8w+8)
    const u64* base = g_cand + (w * 8) * KKEY;
    u64 v0 = base[lane];
    u64 v1 = base[32 + lane];
#pragma unroll
    for (int l = 1; l < 8; l++) {
        u64 b0 = base[l * KKEY + lane];
        u64 b1 = base[l * KKEY + 32 + lane];
        warp_merge64(v0, v1, b0, b1, lane);
    }

    // block-level: 16 lists -> 1 (4 rounds)
    for (int nl = 16; nl > 1; nl >>= 1) {
        int half = nl >> 1;
        __syncthreads();
        if (w >= half && w < nl) {
            sx[(w - half) * 64 + lane] = v0;
            sx[(w - half) * 64 + 32 + lane] = v1;
        }
        __syncthreads();
        if (w < half) {
            u64 b0 = sx[w * 64 + lane];
            u64 b1 = sx[w * 64 + 32 + lane];
            warp_merge64(v0, v1, b0, b1, lane);
        }
    }
    if (w == 0) {
        sidx[lane]      = (int)(~(unsigned int)v0);
        sidx[lane + 32] = (int)(~(unsigned int)v1);
    }
    __syncthreads();

    // fused gather: out[b,k,c] = src_pts[b, c, idx[k]]   (8,64,6) row-major
#pragma unroll
    for (int o = t; o < 8 * KKEY * 6; o += 512) {
        int c = o % 6;
        int k = (o / 6) & (KKEY - 1);
        int b = o / (6 * KKEY);
        out[o] = src[(b * 6 + c) * N_PTS + sidx[k]];
    }
}

// ---------------------------------------------------------------------------
extern "C" void kernel_launch(void* const* d_in, const int* in_sizes, int n_in,
                              void* d_out, int out_size)
{
    const float* src = (const float*)d_in[0];   // src_pts (8,6,65536)
    // d_in[1] = tgt_pts (unused)
    const float* W1 = (const float*)d_in[2];
    const float* b1 = (const float*)d_in[3];
    const float* W2 = (const float*)d_in[4];
    const float* b2 = (const float*)d_in[5];
    const float* Wa = (const float*)d_in[6];
    const float* ba = (const float*)d_in[7];
    const float* Wb = (const float*)d_in[8];
    const float* bb = (const float*)d_in[9];
    const float* Wc = (const float*)d_in[10];
    const float* bc = (const float*)d_in[11];
    float* out = (float*)d_out;

    score_kernel<<<GRID_SCORE, NT>>>(
        src, W1, b1, W2, b2, Wa, ba, Wb, bb, Wc, bc);
    tail_kernel<<<1, 512>>>(src, out);
}

// round 16
// speedup vs baseline: 1.0727x; 1.0061x over previous
#include <cuda_runtime.h>
#include <math.h>

#define N_PTS 65536
#define KKEY 64
#define NT 512
#define GRID_SCORE 128   // 128 blocks x 512 threads = 65536 points, 1 pt/thread

typedef unsigned long long u64;

// scratch (no allocations allowed) — referenced ONLY from device code
__device__ u64 g_cand[GRID_SCORE * KKEY];   // 8192 (128 sorted-64 lists)
__device__ unsigned g_done;                  // zero-init; reset by elected block

// ---------------------------------------------------------------------------
// packed f32x2 helpers (FFMA2: 2 fp32 FMAs per instruction, only via PTX)
// ---------------------------------------------------------------------------
__device__ __forceinline__ u64 fma2(u64 a, u64 b, u64 c) {
    u64 d;
    asm("fma.rn.f32x2 %0, %1, %2, %3;" : "=l"(d) : "l"(a), "l"(b), "l"(c));
    return d;
}
__device__ __forceinline__ u64 add2(u64 a, u64 b) {
    u64 d;
    asm("add.rn.f32x2 %0, %1, %2;" : "=l"(d) : "l"(a), "l"(b));
    return d;
}
__device__ __forceinline__ u64 pack2(float lo, float hi) {
    u64 r;
    asm("mov.b64 %0, {%1, %2};" : "=l"(r) : "f"(lo), "f"(hi));
    return r;
}
__device__ __forceinline__ void unpack2(u64 x, float& lo, float& hi) {
    asm("mov.b64 {%0, %1}, %2;" : "=f"(lo), "=f"(hi) : "l"(x));
}
__device__ __forceinline__ u64 relu2(u64 x) {
    float lo, hi;
    unpack2(x, lo, hi);
    return pack2(fmaxf(lo, 0.0f), fmaxf(hi, 0.0f));
}

// ---------------------------------------------------------------------------
// bitonic compare-select, element at global position i, descending sort.
// Keys unique (low bits = ~index) so strict compare is fine.
// ---------------------------------------------------------------------------
__device__ __forceinline__ u64 cmpsel(u64 v, u64 pv, int i, int k, int j) {
    bool keep_max = (((i & k) == 0) == ((i & j) == 0));
    u64 mx = v > pv ? v : pv;
    u64 mn = v > pv ? pv : v;
    return keep_max ? mx : mn;
}

// ---------------------------------------------------------------------------
// warp-local sort of 64 elements (v0 = pos lane, v1 = pos lane+32),
// descending, barrier-free (shfl only; j==32 is in-thread).
// ---------------------------------------------------------------------------
__device__ __forceinline__ void warp_sort64(u64& v0, u64& v1, int lane) {
#pragma unroll
    for (int k = 2; k <= 64; k <<= 1) {
#pragma unroll
        for (int j = k >> 1; j > 0; j >>= 1) {
            if (j == 32) {
                bool dirdesc = ((lane & k) == 0);
                u64 mx = v0 > v1 ? v0 : v1;
                u64 mn = v0 > v1 ? v1 : v0;
                v0 = dirdesc ? mx : mn;
                v1 = dirdesc ? mn : mx;
            } else {
                u64 p0 = __shfl_xor_sync(0xffffffffu, v0, j);
                u64 p1 = __shfl_xor_sync(0xffffffffu, v1, j);
                v0 = cmpsel(v0, p0, lane, k, j);
                v1 = cmpsel(v1, p1, lane + 32, k, j);
            }
        }
    }
}

// ---------------------------------------------------------------------------
// merge two sorted-descending 64-lists, keeping the sorted top-64 in (a0,a1).
// w[i] = max(A[i], B[63-i]) is bitonic and contains the top-64; then a
// 6-substage descending bitonic merge. Barrier-free.
// ---------------------------------------------------------------------------
__device__ __forceinline__ void warp_merge64(u64& a0, u64& a1, u64 b0, u64 b1,
                                             int lane) {
    u64 rb1 = __shfl_sync(0xffffffffu, b1, 31 - lane);  // B[63-lane]
    u64 rb0 = __shfl_sync(0xffffffffu, b0, 31 - lane);  // B[63-(lane+32)]
    u64 w0 = a0 > rb1 ? a0 : rb1;
    u64 w1 = a1 > rb0 ? a1 : rb0;
    {
        u64 mx = w0 > w1 ? w0 : w1;
        u64 mn = w0 > w1 ? w1 : w0;
        w0 = mx; w1 = mn;
    }
#pragma unroll
    for (int j = 16; j > 0; j >>= 1) {
        u64 p0 = __shfl_xor_sync(0xffffffffu, w0, j);
        u64 p1 = __shfl_xor_sync(0xffffffffu, w1, j);
        bool low = ((lane & j) == 0);
        w0 = low ? (w0 > p0 ? w0 : p0) : (w0 < p0 ? w0 : p0);
        w1 = low ? (w1 > p1 ? w1 : p1) : (w1 < p1 ? w1 : p1);
    }
    a0 = w0; a1 = w1;
}

// ---------------------------------------------------------------------------
// Epilogue (elected block only): merge all 128 sorted-64 lists -> top-64,
// then fused gather. __noinline__ so its register demand and scheduling do
// NOT perturb the hot score path (the R14 regression).
// ---------------------------------------------------------------------------
__device__ __noinline__ void epilogue(const float* __restrict__ src,
                                      float* __restrict__ out,
                                      u64* sx, int* sidx,
                                      int t, int lane, int w)
{
    // each warp folds lists [8w, 8w+8) (barrier-free serial merges)
    const u64* base = g_cand + (w * 8) * KKEY;
    u64 v0 = base[lane];
    u64 v1 = base[32 + lane];
#pragma unroll
    for (int l = 1; l < 8; l++) {
        u64 b0 = base[l * KKEY + lane];
        u64 b1 = base[l * KKEY + 32 + lane];
        warp_merge64(v0, v1, b0, b1, lane);
    }

    // block-level: 16 lists -> 1 (4 rounds)
    for (int nl = 16; nl > 1; nl >>= 1) {
        int half = nl >> 1;
        __syncthreads();
        if (w >= half && w < nl) {
            sx[(w - half) * 64 + lane] = v0;
            sx[(w - half) * 64 + 32 + lane] = v1;
        }
        __syncthreads();
        if (w < half) {
            u64 b0 = sx[w * 64 + lane];
            u64 b1 = sx[w * 64 + 32 + lane];
            warp_merge64(v0, v1, b0, b1, lane);
        }
    }
    if (w == 0) {
        sidx[lane]      = (int)(~(unsigned int)v0);
        sidx[lane + 32] = (int)(~(unsigned int)v1);
    }
    __syncthreads();

    // fused gather: out[b,k,c] = src_pts[b, c, idx[k]]   (8,64,6) row-major
    for (int o = t; o < 8 * KKEY * 6; o += NT) {
        int c = o % 6;
        int k = (o / 6) & (KKEY - 1);
        int b = o / (6 * KKEY);
        out[o] = src[(b * 6 + c) * N_PTS + sidx[k]];
    }

    __syncthreads();
    if (t == 0) g_done = 0u;   // reset for graph replay; elected block is last
}

// ---------------------------------------------------------------------------
// ONE kernel: MLP score (R13-verbatim math + selection), per-block sorted
// top-64 into g_cand, last-finisher election, noinline epilogue.
// key = (bits(softplus) << 32) | ~n  (sp > 0 so bits are order-monotonic)
// ---------------------------------------------------------------------------
__global__ __launch_bounds__(NT) void fused_kernel(
    const float* __restrict__ src,
    const float* __restrict__ W1, const float* __restrict__ b1,
    const float* __restrict__ W2, const float* __restrict__ b2,
    const float* __restrict__ Wa, const float* __restrict__ ba,
    const float* __restrict__ Wb, const float* __restrict__ bb_,
    const float* __restrict__ Wc, const float* __restrict__ bc,
    float* __restrict__ out)
{
    __shared__ __align__(16) u64 sW1p[96];     // [i<16][c<6] = (W1[2i,c], W1[2i+1,c])
    __shared__ __align__(16) u64 sW2p[1024];   // [j<64][i<16] = (W2[j,2i], W2[j,2i+1])
    __shared__ __align__(16) u64 sWaJp[512];   // [jp<32][i<16] = (Wa[i,2jp], Wa[i,2jp+1])
    __shared__ __align__(16) u64 sWbp[64];     // [i<4][k<16] = (Wb[2i,k], Wb[2i+1,k])
    __shared__ __align__(16) u64 sWcp[4];      // (Wc[2i], Wc[2i+1])
    __shared__ u64 sb1p[16];                   // (b1[2i], b1[2i+1])
    __shared__ u64 sb2p[32];                   // (b2[2jp], b2[2jp+1])
    __shared__ float sba[16];
    __shared__ u64 sbbp[4];
    __shared__ float sbc;
    __shared__ u64 s_keys[NT];
    __shared__ int sidx[KKEY];
    __shared__ unsigned s_old;

    const int t = threadIdx.x;
    const int blk = blockIdx.x;
    const int lane = t & 31;
    const int w = t >> 5;

    // W2 rows are contiguous fp32 -> natural u64 pairs, direct copy
    for (int i = t; i < 1024; i += NT)
        sW2p[i] = ((const u64*)W2)[i];
    for (int idx = t; idx < 512; idx += NT) {
        int jp = idx >> 4, i = idx & 15;
        sWaJp[idx] = pack2(Wa[i * 64 + 2 * jp], Wa[i * 64 + 2 * jp + 1]);
    }
    if (t < 96) {
        int i = t / 6, c = t % 6;
        sW1p[t] = pack2(W1[(2 * i) * 6 + c], W1[(2 * i + 1) * 6 + c]);
    }
    if (t >= 96 && t < 112)  sb1p[t - 96] = pack2(b1[2 * (t - 96)], b1[2 * (t - 96) + 1]);
    if (t >= 112 && t < 128) sba[t - 112] = ba[t - 112];
    if (t >= 128 && t < 192) {
        int idx = t - 128;
        int i = idx >> 4, k = idx & 15;
        sWbp[idx] = pack2(Wb[(2 * i) * 16 + k], Wb[(2 * i + 1) * 16 + k]);
    }
    if (t >= 192 && t < 224) sb2p[t - 192] = ((const u64*)b2)[t - 192];
    if (t >= 224 && t < 228) sbbp[t - 224] = pack2(bb_[2 * (t - 224)], bb_[2 * (t - 224) + 1]);
    if (t >= 228 && t < 232) sWcp[t - 228] = pack2(Wc[2 * (t - 228)], Wc[2 * (t - 228) + 1]);
    if (t == 0) sbc = bc[0];
    __syncthreads();

    const int n = blk * NT + t;   // point id

    u64 xd[6];
#pragma unroll
    for (int c = 0; c < 6; c++) {
        float xv = src[c * N_PTS + n];
        xd[c] = pack2(xv, xv);
    }

    // layer 1: 6 -> 32 (as 16 neuron-pairs), relu
    u64 h1p[16];
#pragma unroll
    for (int i = 0; i < 16; i++) {
        const ulonglong2* wq = (const ulonglong2*)(sW1p + i * 6);
        ulonglong2 q0 = wq[0], q1 = wq[1], q2 = wq[2];
        u64 v = sb1p[i];
        v = fma2(q0.x, xd[0], v);
        v = fma2(q0.y, xd[1], v);
        v = fma2(q1.x, xd[2], v);
        v = fma2(q1.y, xd[3], v);
        v = fma2(q2.x, xd[4], v);
        v = fma2(q2.y, xd[5], v);
        h1p[i] = relu2(v);
    }

    // layer 2 (32->64, relu) fused with layer a (64->16): j-paired
    u64 ap[16];
#pragma unroll
    for (int i = 0; i < 16; i++) ap[i] = pack2(sba[i], 0.0f);

#pragma unroll 2
    for (int jp = 0; jp < 32; jp++) {
        const ulonglong2* w2 = (const ulonglong2*)(sW2p + (2 * jp) * 16);
        u64 cA0 = 0ULL, cA1 = 0ULL, cB0 = 0ULL, cB1 = 0ULL;
#pragma unroll
        for (int i = 0; i < 16; i += 4) {
            ulonglong2 qa0 = w2[i / 2];
            ulonglong2 qa1 = w2[i / 2 + 1];
            ulonglong2 qb0 = w2[8 + i / 2];
            ulonglong2 qb1 = w2[8 + i / 2 + 1];
            cA0 = fma2(qa0.x, h1p[i],     cA0);
            cA1 = fma2(qa0.y, h1p[i + 1], cA1);
            cA0 = fma2(qa1.x, h1p[i + 2], cA0);
            cA1 = fma2(qa1.y, h1p[i + 3], cA1);
            cB0 = fma2(qb0.x, h1p[i],     cB0);
            cB1 = fma2(qb0.y, h1p[i + 1], cB1);
            cB0 = fma2(qb1.x, h1p[i + 2], cB0);
            cB1 = fma2(qb1.y, h1p[i + 3], cB1);
        }
        u64 sA = add2(cA0, cA1);
        u64 sB = add2(cB0, cB1);
        float alo, ahi, blo, bhi;
        unpack2(sA, alo, ahi);
        unpack2(sB, blo, bhi);
        u64 sum = add2(add2(pack2(alo, blo), pack2(ahi, bhi)), sb2p[jp]);
        float v0f, v1f;
        unpack2(sum, v0f, v1f);
        u64 vd = pack2(fmaxf(v0f, 0.0f), fmaxf(v1f, 0.0f));

        const ulonglong2* wa = (const ulonglong2*)(sWaJp + jp * 16);
#pragma unroll
        for (int i = 0; i < 16; i += 2) {
            ulonglong2 q = wa[i / 2];
            ap[i]     = fma2(q.x, vd, ap[i]);
            ap[i + 1] = fma2(q.y, vd, ap[i + 1]);
        }
    }

    // horizontalize layer-a accumulators; relu; dup for layer b
    u64 afd[16];
#pragma unroll
    for (int i = 0; i < 16; i++) {
        float lo, hi;
        unpack2(ap[i], lo, hi);
        float av = fmaxf(lo + hi, 0.0f);
        afd[i] = pack2(av, av);
    }

    // layer b: 16 -> 8 (as 4 neuron-pairs), relu
    u64 hbp[4];
#pragma unroll
    for (int i = 0; i < 4; i++) {
        const ulonglong2* wb = (const ulonglong2*)(sWbp + i * 16);
        u64 s0 = sbbp[i], s1 = 0ULL;
#pragma unroll
        for (int k = 0; k < 16; k += 4) {
            ulonglong2 q0 = wb[k / 2];
            ulonglong2 q1 = wb[k / 2 + 1];
            s0 = fma2(q0.x, afd[k],     s0);
            s1 = fma2(q0.y, afd[k + 1], s1);
            s0 = fma2(q1.x, afd[k + 2], s0);
            s1 = fma2(q1.y, afd[k + 3], s1);
        }
        hbp[i] = relu2(add2(s0, s1));
    }

    // layer c: 8 -> 1, softplus = max(x,0)+log1p(exp(-|x|))
    u64 cp = 0ULL;
#pragma unroll
    for (int i = 0; i < 4; i++) cp = fma2(sWcp[i], hbp[i], cp);
    float clo, chi;
    unpack2(cp, clo, chi);
    float c0f = sbc + (clo + chi);
    float sp = fmaxf(c0f, 0.0f) + log1pf(expf(-fabsf(c0f)));

    s_keys[t] = ((u64)__float_as_uint(sp) << 32) | (unsigned int)(~n);
    __syncthreads();

    // selection: warps 0..7 sort 64-chunks, then 3 merge levels -> top-64
    {
        u64 v0 = 0ULL, v1 = 0ULL;
        if (w < 8) {
            v0 = s_keys[w * 64 + lane];
            v1 = s_keys[w * 64 + 32 + lane];
            warp_sort64(v0, v1, lane);
        }
        for (int nl = 8; nl > 1; nl >>= 1) {
            int half = nl >> 1;
            __syncthreads();
            if (w >= half && w < nl) {
                s_keys[(w - half) * 64 + lane] = v0;
                s_keys[(w - half) * 64 + 32 + lane] = v1;
            }
            __syncthreads();
            if (w < half) {
                u64 b0 = s_keys[w * 64 + lane];
                u64 b1 = s_keys[w * 64 + 32 + lane];
                warp_merge64(v0, v1, b0, b1, lane);
            }
        }
        if (w == 0) {
            g_cand[blk * KKEY + lane] = v0;
            g_cand[blk * KKEY + 32 + lane] = v1;
        }
    }

    // ---- election: last block to finish runs the epilogue ----
    __threadfence();
    __syncthreads();
    if (t == 0) s_old = atomicAdd(&g_done, 1u);
    __syncthreads();
    if (s_old != GRID_SCORE - 1) return;
    __threadfence();

    epilogue(src, out, s_keys, sidx, t, lane, w);
}

// ---------------------------------------------------------------------------
extern "C" void kernel_launch(void* const* d_in, const int* in_sizes, int n_in,
                              void* d_out, int out_size)
{
    const float* src = (const float*)d_in[0];   // src_pts (8,6,65536)
    // d_in[1] = tgt_pts (unused)
    const float* W1 = (const float*)d_in[2];
    const float* b1 = (const float*)d_in[3];
    const float* W2 = (const float*)d_in[4];
    const float* b2 = (const float*)d_in[5];
    const float* Wa = (const float*)d_in[6];
    const float* ba = (const float*)d_in[7];
    const float* Wb = (const float*)d_in[8];
    const float* bb = (const float*)d_in[9];
    const float* Wc = (const float*)d_in[10];
    const float* bc = (const float*)d_in[11];
    float* out = (float*)d_out;

    fused_kernel<<<GRID_SCORE, NT>>>(
        src, W1, b1, W2, b2, Wa, ba, Wb, bb, Wc, bc, out);
}